// round 4
// baseline (speedup 1.0000x reference)
#include <cuda_runtime.h>

#define BB 16
#define SS 4096
#define DD 1024
#define THREADS 256
#define WARPS (THREADS / 32)
#define GRID 1024

__global__ void zero_out_kernel(float* __restrict__ out) {
    if (threadIdx.x < BB) out[threadIdx.x] = 0.0f;
}

__global__ __launch_bounds__(THREADS)
void ic_reward_kernel(const float* __restrict__ x,
                      const float* __restrict__ W,
                      const float* __restrict__ b,
                      const int* __restrict__ lengths,
                      float* __restrict__ out) {
    __shared__ int cum_s[BB + 1];   // exclusive prefix sum of lengths
    __shared__ float bsum[BB];      // per-block per-batch partial sums

    if (threadIdx.x == 0) {
        int c = 0;
        #pragma unroll
        for (int i = 0; i < BB; i++) { cum_s[i] = c; c += lengths[i]; }
        cum_s[BB] = c;
    }
    if (threadIdx.x < BB) bsum[threadIdx.x] = 0.0f;
    __syncthreads();

    const int V = cum_s[BB];            // total valid rows (compacted work space)
    const int warp = threadIdx.x >> 5;
    const int lane = threadIdx.x & 31;

    // W hoisted to registers: each lane's slice is row-invariant (64 regs).
    float4 w0r[8], w1r[8];
    #pragma unroll
    for (int k = 0; k < 8; k++) {
        const int idx = k * 32 + lane;
        w0r[k] = reinterpret_cast<const float4*>(W)[idx];
        w1r[k] = reinterpret_cast<const float4*>(W + DD)[idx];
    }
    const float b0 = b[0];
    const float b1 = b[1];

    const int gw = blockIdx.x * WARPS + warp;   // global warp id
    const int nw = GRID * WARPS;                // total warps in grid

    // Grid-stride over COMPACTED valid rows: every warp gets V/nw (+-1) rows,
    // independent of how lengths are distributed across batches.
    for (int v = gw; v < V; v += nw) {
        // v -> (batch, row): branchless scan of the 16-entry prefix sum
        int batch = 0;
        #pragma unroll
        for (int i = 1; i < BB; i++) batch += (v >= cum_s[i]) ? 1 : 0;
        const int row = v - cum_s[batch];

        const float4* xr = reinterpret_cast<const float4*>(
            x + ((size_t)batch * SS + (size_t)row) * DD);

        float s0 = 0.0f, s1 = 0.0f;
        #pragma unroll
        for (int k = 0; k < 8; k++) {
            const float4 xv = xr[k * 32 + lane];   // coalesced LDG.128
            s0 += xv.x * w0r[k].x + xv.y * w0r[k].y + xv.z * w0r[k].z + xv.w * w0r[k].w;
            s1 += xv.x * w1r[k].x + xv.y * w1r[k].y + xv.z * w1r[k].z + xv.w * w1r[k].w;
        }

        // warp tree reduction of both partial dots
        #pragma unroll
        for (int o = 16; o > 0; o >>= 1) {
            s0 += __shfl_xor_sync(0xFFFFFFFFu, s0, o);
            s1 += __shfl_xor_sync(0xFFFFFFFFu, s1, o);
        }

        if (lane == 0) {
            const float gate = 1.0f / (1.0f + __expf(-(s0 + b0)));
            atomicAdd(&bsum[batch], gate * (s1 + b1));   // smem atomic: ~32cyc, noise
        }
    }

    __syncthreads();
    if (threadIdx.x < BB) {
        const float vsum = bsum[threadIdx.x];
        if (vsum != 0.0f) atomicAdd(&out[threadIdx.x], vsum);
    }
}

extern "C" void kernel_launch(void* const* d_in, const int* in_sizes, int n_in,
                              void* d_out, int out_size) {
    const float* x       = (const float*)d_in[0];
    const float* W       = (const float*)d_in[1];
    const float* b       = (const float*)d_in[2];
    const int*   lengths = (const int*)d_in[3];
    float* out = (float*)d_out;

    zero_out_kernel<<<1, 32>>>(out);
    ic_reward_kernel<<<GRID, THREADS>>>(x, W, b, lengths, out);
}

// round 6
// speedup vs baseline: 1.1033x; 1.1033x over previous
#include <cuda_runtime.h>

#define BB 16
#define SS 4096
#define DD 1024
#define THREADS 256
#define WARPS 8
#define GRID 296                      // 2 CTAs/SM x 148 SMs = single wave
#define NWT (GRID * WARPS)            // total warps

__global__ void zero_out_kernel(float* __restrict__ out) {
    if (threadIdx.x < BB) out[threadIdx.x] = 0.0f;
}

template<int NR>
__device__ __forceinline__ void process_rows(
    int v0, const int* __restrict__ cum_s,
    const float4* __restrict__ w0s, const float4* __restrict__ w1s,
    const float* __restrict__ x, int lane, float b0, float b1,
    float* __restrict__ bsum)
{
    int bat[NR];
    const float4* xr[NR];
    #pragma unroll
    for (int r = 0; r < NR; r++) {
        const int vr = v0 + r;
        int batch = 0;
        #pragma unroll
        for (int i = 1; i < BB; i++) batch += (vr >= cum_s[i]) ? 1 : 0;
        bat[r] = batch;
        const int row = vr - cum_s[batch];
        xr[r] = reinterpret_cast<const float4*>(
            x + ((size_t)batch * SS + (size_t)row) * DD);
    }

    float s0[NR], s1[NR];
    #pragma unroll
    for (int r = 0; r < NR; r++) { s0[r] = 0.0f; s1[r] = 0.0f; }

    // NR independent row streams: up to NR*8 LDG.128 in flight per warp.
    #pragma unroll
    for (int k = 0; k < 8; k++) {
        const int idx = k * 32 + lane;               // coalesced, conflict-free
        const float4 w0 = w0s[idx];
        const float4 w1 = w1s[idx];
        #pragma unroll
        for (int r = 0; r < NR; r++) {
            const float4 xv = xr[r][idx];            // LDG.128
            s0[r] += xv.x * w0.x + xv.y * w0.y + xv.z * w0.z + xv.w * w0.w;
            s1[r] += xv.x * w1.x + xv.y * w1.y + xv.z * w1.z + xv.w * w1.w;
        }
    }

    // Interleaved warp tree reductions — shuffle chains pipeline.
    #pragma unroll
    for (int o = 16; o > 0; o >>= 1) {
        #pragma unroll
        for (int r = 0; r < NR; r++) {
            s0[r] += __shfl_xor_sync(0xFFFFFFFFu, s0[r], o);
            s1[r] += __shfl_xor_sync(0xFFFFFFFFu, s1[r], o);
        }
    }

    if (lane == 0) {
        #pragma unroll
        for (int r = 0; r < NR; r++) {
            const float gate = 1.0f / (1.0f + __expf(-(s0[r] + b0)));
            atomicAdd(&bsum[bat[r]], gate * (s1[r] + b1));
        }
    }
}

__global__ __launch_bounds__(THREADS, 2)
void ic_reward_kernel(const float* __restrict__ x,
                      const float* __restrict__ W,
                      const float* __restrict__ b,
                      const int* __restrict__ lengths,
                      float* __restrict__ out) {
    __shared__ float4 w0s[DD / 4];
    __shared__ float4 w1s[DD / 4];
    __shared__ int cum_s[BB + 1];
    __shared__ float bsum[BB];

    for (int i = threadIdx.x; i < DD / 4; i += THREADS) {
        w0s[i] = reinterpret_cast<const float4*>(W)[i];
        w1s[i] = reinterpret_cast<const float4*>(W + DD)[i];
    }
    if (threadIdx.x == 0) {
        int c = 0;
        #pragma unroll
        for (int i = 0; i < BB; i++) { cum_s[i] = c; c += lengths[i]; }
        cum_s[BB] = c;
    }
    if (threadIdx.x < BB) bsum[threadIdx.x] = 0.0f;
    __syncthreads();

    const int V = cum_s[BB];
    const int warp = threadIdx.x >> 5;
    const int lane = threadIdx.x & 31;
    const float b0 = b[0];
    const float b1 = b[1];

    // Balanced contiguous span of the compacted valid-row space: +-1 row skew.
    const int gw = blockIdx.x * WARPS + warp;
    int v       = (int)(((long long)V * gw) / NWT);
    const int e = (int)(((long long)V * (gw + 1)) / NWT);

    for (; v + 4 <= e; v += 4)
        process_rows<4>(v, cum_s, w0s, w1s, x, lane, b0, b1, bsum);
    if (v + 2 <= e) {
        process_rows<2>(v, cum_s, w0s, w1s, x, lane, b0, b1, bsum);
        v += 2;
    }
    if (v < e)
        process_rows<1>(v, cum_s, w0s, w1s, x, lane, b0, b1, bsum);

    __syncthreads();
    if (threadIdx.x < BB) {
        const float t = bsum[threadIdx.x];
        if (t != 0.0f) atomicAdd(&out[threadIdx.x], t);
    }
}

extern "C" void kernel_launch(void* const* d_in, const int* in_sizes, int n_in,
                              void* d_out, int out_size) {
    const float* x       = (const float*)d_in[0];
    const float* W       = (const float*)d_in[1];
    const float* b       = (const float*)d_in[2];
    const int*   lengths = (const int*)d_in[3];
    float* out = (float*)d_out;

    zero_out_kernel<<<1, 32>>>(out);
    ic_reward_kernel<<<GRID, THREADS>>>(x, W, b, lengths, out);
}

// round 7
// speedup vs baseline: 1.1047x; 1.0013x over previous
#include <cuda_runtime.h>

#define BB 16
#define SS 4096
#define DD 1024
#define THREADS 256
#define WARPS 8
#define GRID 444                      // 3 CTAs/SM x 148 SMs = single wave
#define NWT (GRID * WARPS)            // total warps

__global__ void zero_out_kernel(float* __restrict__ out) {
    if (threadIdx.x < BB) out[threadIdx.x] = 0.0f;
}

__device__ __forceinline__ float4 ldcs4(const float4* p) {
    return __ldcs(p);                 // streaming load: x has zero reuse
}

__global__ __launch_bounds__(THREADS, 3)
void ic_reward_kernel(const float* __restrict__ x,
                      const float* __restrict__ W,
                      const float* __restrict__ b,
                      const int* __restrict__ lengths,
                      float* __restrict__ out) {
    __shared__ float4 w0s[DD / 4];
    __shared__ float4 w1s[DD / 4];
    __shared__ int cum_s[BB + 1];
    __shared__ float bsum[BB];

    for (int i = threadIdx.x; i < DD / 4; i += THREADS) {
        w0s[i] = reinterpret_cast<const float4*>(W)[i];
        w1s[i] = reinterpret_cast<const float4*>(W + DD)[i];
    }
    if (threadIdx.x == 0) {
        int c = 0;
        #pragma unroll
        for (int i = 0; i < BB; i++) { cum_s[i] = c; c += lengths[i]; }
        cum_s[BB] = c;
    }
    if (threadIdx.x < BB) bsum[threadIdx.x] = 0.0f;
    __syncthreads();

    const int V = cum_s[BB];
    const int warp = threadIdx.x >> 5;
    const int lane = threadIdx.x & 31;
    const float b0 = b[0];
    const float b1 = b[1];

    // Balanced contiguous span of the compacted valid-row space: +-1 row skew.
    const int gw = blockIdx.x * WARPS + warp;
    int v       = (int)(((long long)V * gw) / NWT);
    const int e = (int)(((long long)V * (gw + 1)) / NWT);

    // -------- main loop: 2 independent row streams (16 LDG.128 in flight) ----
    for (; v + 2 <= e; v += 2) {
        int batA = 0, batB = 0;
        #pragma unroll
        for (int i = 1; i < BB; i++) {
            batA += (v     >= cum_s[i]) ? 1 : 0;
            batB += (v + 1 >= cum_s[i]) ? 1 : 0;
        }
        const float4* xrA = reinterpret_cast<const float4*>(
            x + ((size_t)batA * SS + (size_t)(v     - cum_s[batA])) * DD);
        const float4* xrB = reinterpret_cast<const float4*>(
            x + ((size_t)batB * SS + (size_t)(v + 1 - cum_s[batB])) * DD);

        float a0 = 0.0f, a1 = 0.0f, c0 = 0.0f, c1 = 0.0f;
        #pragma unroll
        for (int k = 0; k < 8; k++) {
            const int idx = k * 32 + lane;           // coalesced LDG.128
            const float4 xa = ldcs4(&xrA[idx]);
            const float4 xb = ldcs4(&xrB[idx]);
            const float4 w0 = w0s[idx];
            const float4 w1 = w1s[idx];
            a0 += xa.x * w0.x + xa.y * w0.y + xa.z * w0.z + xa.w * w0.w;
            a1 += xa.x * w1.x + xa.y * w1.y + xa.z * w1.z + xa.w * w1.w;
            c0 += xb.x * w0.x + xb.y * w0.y + xb.z * w0.z + xb.w * w0.w;
            c1 += xb.x * w1.x + xb.y * w1.y + xb.z * w1.z + xb.w * w1.w;
        }

        #pragma unroll
        for (int o = 16; o > 0; o >>= 1) {
            a0 += __shfl_xor_sync(0xFFFFFFFFu, a0, o);
            a1 += __shfl_xor_sync(0xFFFFFFFFu, a1, o);
            c0 += __shfl_xor_sync(0xFFFFFFFFu, c0, o);
            c1 += __shfl_xor_sync(0xFFFFFFFFu, c1, o);
        }

        if (lane == 0) {
            const float gA = 1.0f / (1.0f + __expf(-(a0 + b0)));
            atomicAdd(&bsum[batA], gA * (a1 + b1));
            const float gB = 1.0f / (1.0f + __expf(-(c0 + b0)));
            atomicAdd(&bsum[batB], gB * (c1 + b1));
        }
    }

    // -------- tail: single row ----------------------------------------------
    if (v < e) {
        int batch = 0;
        #pragma unroll
        for (int i = 1; i < BB; i++) batch += (v >= cum_s[i]) ? 1 : 0;
        const float4* xr = reinterpret_cast<const float4*>(
            x + ((size_t)batch * SS + (size_t)(v - cum_s[batch])) * DD);

        float s0 = 0.0f, s1 = 0.0f;
        #pragma unroll
        for (int k = 0; k < 8; k++) {
            const int idx = k * 32 + lane;
            const float4 xv = ldcs4(&xr[idx]);
            const float4 w0 = w0s[idx];
            const float4 w1 = w1s[idx];
            s0 += xv.x * w0.x + xv.y * w0.y + xv.z * w0.z + xv.w * w0.w;
            s1 += xv.x * w1.x + xv.y * w1.y + xv.z * w1.z + xv.w * w1.w;
        }
        #pragma unroll
        for (int o = 16; o > 0; o >>= 1) {
            s0 += __shfl_xor_sync(0xFFFFFFFFu, s0, o);
            s1 += __shfl_xor_sync(0xFFFFFFFFu, s1, o);
        }
        if (lane == 0) {
            const float gate = 1.0f / (1.0f + __expf(-(s0 + b0)));
            atomicAdd(&bsum[batch], gate * (s1 + b1));
        }
    }

    __syncthreads();
    if (threadIdx.x < BB) {
        const float t = bsum[threadIdx.x];
        if (t != 0.0f) atomicAdd(&out[threadIdx.x], t);
    }
}

extern "C" void kernel_launch(void* const* d_in, const int* in_sizes, int n_in,
                              void* d_out, int out_size) {
    const float* x       = (const float*)d_in[0];
    const float* W       = (const float*)d_in[1];
    const float* b       = (const float*)d_in[2];
    const int*   lengths = (const int*)d_in[3];
    float* out = (float*)d_out;

    zero_out_kernel<<<1, 32>>>(out);
    ic_reward_kernel<<<GRID, THREADS>>>(x, W, b, lengths, out);
}